// round 2
// baseline (speedup 1.0000x reference)
#include <cuda_runtime.h>
#include <math.h>

#define B_   16
#define T_   8
#define C_   2048
#define H_   16
#define D_   128
#define MAXSEQ 4096
#define M_   (B_*T_)      // 128
#define N3_  (3*C_)       // 6144
#define NS   16           // kv splits
#define CHUNK (MAXSEQ/NS) // 256 keys per split
#define KSTRIDE 132       // padded K-tile row stride (floats)

// ---------------- scratch ----------------
__device__ __align__(16) float g_qkv[M_ * N3_];
__device__ __align__(16) float g_part[4 * M_ * N3_ / 2 + M_ * N3_];  // >= max(4*M*N3, 8*M*C)
__device__ __align__(16) float g_pacc[B_*H_ * NS * T_ * D_];
__device__ __align__(16) float g_pl[B_*H_ * NS * T_];
__device__ __align__(16) float g_y[M_ * C_];

// ---------------- f32x2 helpers ----------------
__device__ __forceinline__ void fma2(unsigned long long& d,
                                     unsigned long long a,
                                     unsigned long long b) {
    asm("fma.rn.f32x2 %0, %1, %2, %0;" : "+l"(d) : "l"(a), "l"(b));
}
__device__ __forceinline__ unsigned long long pk(float x, float y) {
    unsigned long long r;
    asm("mov.b64 %0, {%1, %2};" : "=l"(r) : "f"(x), "f"(y));
    return r;
}
__device__ __forceinline__ void unpk(unsigned long long d, float& x, float& y) {
    asm("mov.b64 {%0, %1}, %2;" : "=f"(x), "=f"(y) : "l"(d));
}
__device__ __forceinline__ float ex2(float x) {
    float r; asm("ex2.approx.f32 %0, %1;" : "=f"(r) : "f"(x)); return r;
}

// ---------------- split-K SGEMM: Part[z] = A[:, kz] @ B[kz, :] ----------------
// BM=64, BN=64, BK=16, 256 threads, 4x4 per thread via FFMA2 (n-pairs)
__global__ __launch_bounds__(256) void sgemm_sk(
    const float* __restrict__ A, const float* __restrict__ Bm,
    float* __restrict__ Part, int K, int N, int kc)
{
    __shared__ float As[16][64];  // [k][m]
    __shared__ float Bs[16][64];  // [k][n]
    const int tid = threadIdx.x;
    const int m0 = blockIdx.y * 64;
    const int n0 = blockIdx.x * 64;
    const int z  = blockIdx.z;
    const int ty = tid >> 4;          // 0..15 -> m-sub
    const int tx = tid & 15;          // 0..15 -> n-sub

    unsigned long long acc[4][2];
#pragma unroll
    for (int i = 0; i < 4; i++) { acc[i][0] = 0ull; acc[i][1] = 0ull; }

    const int kbeg = z * kc, kend = kbeg + kc;
    // staging indices
    const int ar = tid >> 2, ac4 = (tid & 3) * 4;     // A: 64 rows x 16
    const int br = tid >> 4, bc4 = (tid & 15) * 4;    // B: 16 rows x 64

    for (int k0 = kbeg; k0 < kend; k0 += 16) {
        float4 av = *(const float4*)(A + (size_t)(m0 + ar) * K + k0 + ac4);
        As[ac4 + 0][ar] = av.x; As[ac4 + 1][ar] = av.y;
        As[ac4 + 2][ar] = av.z; As[ac4 + 3][ar] = av.w;
        *(float4*)(&Bs[br][bc4]) =
            *(const float4*)(Bm + (size_t)(k0 + br) * N + n0 + bc4);
        __syncthreads();
#pragma unroll
        for (int k = 0; k < 16; k++) {
            float4 a4 = *(const float4*)(&As[k][ty * 4]);
            ulonglong2 b2 = *(const ulonglong2*)(&Bs[k][tx * 4]);
            unsigned long long ap[4];
            ap[0] = pk(a4.x, a4.x); ap[1] = pk(a4.y, a4.y);
            ap[2] = pk(a4.z, a4.z); ap[3] = pk(a4.w, a4.w);
#pragma unroll
            for (int i = 0; i < 4; i++) {
                fma2(acc[i][0], ap[i], b2.x);
                fma2(acc[i][1], ap[i], b2.y);
            }
        }
        __syncthreads();
    }
    float* dst = Part + (size_t)z * M_ * N + (size_t)(m0 + ty * 4) * N + n0 + tx * 4;
#pragma unroll
    for (int i = 0; i < 4; i++) {
        float4 o;
        unpk(acc[i][0], o.x, o.y);
        unpk(acc[i][1], o.z, o.w);
        *(float4*)(dst + (size_t)i * N) = o;
    }
}

// ---------------- combine split-K partials + bias ----------------
__global__ __launch_bounds__(256) void combine_sk(
    const float* __restrict__ Part, const float* __restrict__ bias,
    float* __restrict__ Out, int MN, int N, int S)
{
    int i4 = blockIdx.x * 256 + threadIdx.x;   // float4 index
    int f = i4 * 4;
    if (f >= MN) return;
    float4 s = *(const float4*)(Part + f);
    for (int z = 1; z < S; z++) {
        float4 p = *(const float4*)(Part + (size_t)z * MN + f);
        s.x += p.x; s.y += p.y; s.z += p.z; s.w += p.w;
    }
    float4 bb = *(const float4*)(bias + (f % N));
    s.x += bb.x; s.y += bb.y; s.z += bb.z; s.w += bb.w;
    *(float4*)(Out + f) = s;
}

// ---------------- attention partials (flash-decoding, no-max softmax) ------
// 2 warps/CTA, each warp one (bh, split). K tile staged in smem (coalesced).
__global__ __launch_bounds__(64) void attn_partial(
    const float* __restrict__ kc, const float* __restrict__ vc,
    const int* __restrict__ p_start, const int* __restrict__ p_causal)
{
    __shared__ float  Qs[T_][D_];            // 4KB, scaled Q
    __shared__ float  Ks[2][32][KSTRIDE];    // 33.8KB
    __shared__ float2 Ps[2][T_][32];         // 4KB, duplicated (p,p)

    const int tid  = threadIdx.x;
    const int w    = tid >> 5;
    const int lane = tid & 31;
    const int bh    = blockIdx.x >> 3;
    const int split = ((blockIdx.x & 7) << 1) | w;
    const int b = bh >> 4, h = bh & 15;

    const int start_pos = *p_start;
    const int causal    = *p_causal;
    const int S = start_pos + T_;
    const float QSCALE = 0.08838834764831845f * 1.4426950408889634f;

    for (int i = tid; i < T_ * 32; i += 64) {
        int t = i >> 5, dq = (i & 31) * 4;
        float4 v = *(const float4*)(g_qkv + (size_t)(b * T_ + t) * N3_ + h * D_ + dq);
        v.x *= QSCALE; v.y *= QSCALE; v.z *= QSCALE; v.w *= QSCALE;
        *(float4*)(&Qs[t][dq]) = v;
    }
    __syncthreads();

    unsigned long long acc[T_][2];
    float lacc[T_];
#pragma unroll
    for (int t = 0; t < T_; t++) { acc[t][0] = 0ull; acc[t][1] = 0ull; lacc[t] = 0.f; }

    const int s0 = split * CHUNK;
    const float* kbase = kc + (size_t)bh * MAXSEQ * D_;
    const float* vbase = vc + (size_t)bh * MAXSEQ * D_;

    for (int tile = 0; tile < CHUNK / 32; tile++) {
        const int sb = s0 + tile * 32;

        // ---- stage K tile: 32 rows, warp-coalesced ----
#pragma unroll 4
        for (int r = 0; r < 32; r++) {
            int s = sb + r;
            float4 kv = make_float4(0.f, 0.f, 0.f, 0.f);
            if (s < S) {
                const float* krow = (s < start_pos)
                    ? (kbase + (size_t)s * D_)
                    : (g_qkv + (size_t)(b * T_ + (s - start_pos)) * N3_ + C_ + h * D_);
                kv = *(const float4*)(krow + lane * 4);
            }
            *(float4*)(&Ks[w][r][lane * 4]) = kv;
        }
        __syncwarp();

        // ---- phase 1: scores, lane owns its key, FFMA2 over d-pairs ----
        unsigned long long sc2[T_];
#pragma unroll
        for (int t = 0; t < T_; t++) sc2[t] = 0ull;
        const float* krow_s = &Ks[w][lane][0];
#pragma unroll 8
        for (int dq = 0; dq < 32; dq++) {
            ulonglong2 k2 = *(const ulonglong2*)(krow_s + dq * 4);
#pragma unroll
            for (int t = 0; t < T_; t++) {
                ulonglong2 q2 = *(const ulonglong2*)(&Qs[t][dq * 4]);
                fma2(sc2[t], q2.x, k2.x);
                fma2(sc2[t], q2.y, k2.y);
            }
        }
        const int s_lane = sb + lane;
        const bool valid = (s_lane < S);
#pragma unroll
        for (int t = 0; t < T_; t++) {
            float a, c; unpk(sc2[t], a, c);
            float p = valid ? ex2(a + c) : 0.f;
            if (causal && s_lane > t) p = 0.f;
            Ps[w][t][lane] = make_float2(p, p);
            lacc[t] += p;
        }
        __syncwarp();

        // ---- phase 2: P @ V, lane owns 4 dims, batched V prefetch ----
#pragma unroll
        for (int jb = 0; jb < 4; jb++) {
            ulonglong2 vv[8];
#pragma unroll
            for (int u = 0; u < 8; u++) {
                int s = sb + jb * 8 + u;
                if (s < S) {
                    const float* vrow = (s < start_pos)
                        ? (vbase + (size_t)s * D_)
                        : (g_qkv + (size_t)(b * T_ + (s - start_pos)) * N3_ + 2 * C_ + h * D_);
                    vv[u] = *(const ulonglong2*)(vrow + lane * 4);
                } else {
                    vv[u].x = 0ull; vv[u].y = 0ull;
                }
            }
#pragma unroll
            for (int u = 0; u < 8; u++) {
                int j = jb * 8 + u;
#pragma unroll
                for (int t = 0; t < T_; t++) {
                    unsigned long long p2 = *(const unsigned long long*)(&Ps[w][t][j]);
                    fma2(acc[t][0], p2, vv[u].x);
                    fma2(acc[t][1], p2, vv[u].y);
                }
            }
        }
        __syncwarp();
    }

    // ---- write partials ----
    const int pbase = (bh * NS + split) * T_;
#pragma unroll
    for (int t = 0; t < T_; t++) {
        float4 o;
        unpk(acc[t][0], o.x, o.y);
        unpk(acc[t][1], o.z, o.w);
        *(float4*)(g_pacc + (size_t)(pbase + t) * D_ + lane * 4) = o;
        float l = lacc[t];
#pragma unroll
        for (int o2 = 16; o2; o2 >>= 1) l += __shfl_xor_sync(0xffffffffu, l, o2);
        if (lane == 0) g_pl[pbase + t] = l;
    }
}

// ---------------- combine attention splits ----------------
__global__ __launch_bounds__(128) void attn_combine()
{
    const int bh = blockIdx.x;
    const int d  = threadIdx.x;
    const int b = bh >> 4, h = bh & 15;
    for (int t = 0; t < T_; t++) {
        float L = 0.f, y = 0.f;
#pragma unroll
        for (int si = 0; si < NS; si++) {
            L += g_pl[(bh * NS + si) * T_ + t];
            y += g_pacc[(size_t)((bh * NS + si) * T_ + t) * D_ + d];
        }
        g_y[(size_t)(b * T_ + t) * C_ + h * D_ + d] = (L > 0.f) ? (y / L) : 0.f;
    }
}

// ---------------- launch ----------------
extern "C" void kernel_launch(void* const* d_in, const int* in_sizes, int n_in,
                              void* d_out, int out_size)
{
    const float* x      = (const float*)d_in[0];
    const float* kc     = (const float*)d_in[1];
    const float* vc     = (const float*)d_in[2];
    const float* w_attn = (const float*)d_in[3];
    const float* b_attn = (const float*)d_in[4];
    const float* w_proj = (const float*)d_in[5];
    const float* b_proj = (const float*)d_in[6];
    const int*   sp     = (const int*)d_in[7];
    const int*   ic     = (const int*)d_in[8];
    float* out = (float*)d_out;

    float* qkv = nullptr; float* y = nullptr; float* part = nullptr;
    cudaGetSymbolAddress((void**)&qkv,  g_qkv);
    cudaGetSymbolAddress((void**)&y,    g_y);
    cudaGetSymbolAddress((void**)&part, g_part);

    // 1) QKV projection, split-K=4
    sgemm_sk<<<dim3(N3_ / 64, M_ / 64, 4), 256>>>(x, w_attn, part, C_, N3_, C_ / 4);
    combine_sk<<<(M_ * N3_ / 4) / 256, 256>>>(part, b_attn, qkv, M_ * N3_, N3_, 4);

    // 2) attention partials + combine
    attn_partial<<<(B_ * H_ * NS) / 2, 64>>>(kc, vc, sp, ic);
    attn_combine<<<B_ * H_, 128>>>();

    // 3) output projection, split-K=8
    sgemm_sk<<<dim3(C_ / 64, M_ / 64, 8), 256>>>(y, w_proj, part, C_, C_, C_ / 8);
    combine_sk<<<(M_ * C_ / 4) / 256, 256>>>(part, b_proj, out, M_ * C_, C_, 8);
}

// round 8
// speedup vs baseline: 1.2568x; 1.2568x over previous
#include <cuda_runtime.h>
#include <cuda_bf16.h>
#include <mma.h>
#include <math.h>
#include <stdint.h>

using namespace nvcuda;

#define B_   16
#define T_   8
#define C_   2048
#define H_   16
#define D_   128
#define MAXSEQ 4096
#define M_   (B_*T_)      // 128
#define N3_  (3*C_)       // 6144
#define NS   16
#define CHUNK (MAXSEQ/NS) // 256
#define KSTRIDE 132

// ---------------- scratch ----------------
__device__ __align__(16) __nv_bfloat16 g_wah[C_ * N3_];
__device__ __align__(16) __nv_bfloat16 g_wal[C_ * N3_];
__device__ __align__(16) __nv_bfloat16 g_wph[C_ * C_];
__device__ __align__(16) __nv_bfloat16 g_wpl[C_ * C_];
__device__ __align__(16) __nv_bfloat16 g_xh[M_ * C_], g_xl[M_ * C_];
__device__ __align__(16) __nv_bfloat16 g_yh[M_ * C_], g_yl[M_ * C_];
__device__ __align__(16) float g_qkv[M_ * N3_];
__device__ __align__(16) float g_part[3 * M_ * N3_];
__device__ __align__(16) float g_pacc[B_*H_ * NS * T_ * D_];
__device__               float g_pl[B_*H_ * NS * T_];
__device__ __align__(16) float g_y[M_ * C_];

// ---------------- helpers ----------------
__device__ __forceinline__ void fma2(unsigned long long& d,
                                     unsigned long long a,
                                     unsigned long long b) {
    asm("fma.rn.f32x2 %0, %1, %2, %0;" : "+l"(d) : "l"(a), "l"(b));
}
__device__ __forceinline__ void unpk(unsigned long long d, float& x, float& y) {
    asm("mov.b64 {%0, %1}, %2;" : "=f"(x), "=f"(y) : "l"(d));
}
__device__ __forceinline__ float ex2(float x) {
    float r; asm("ex2.approx.f32 %0, %1;" : "=f"(r) : "f"(x)); return r;
}

// ---------------- hi/lo split conversion (elementwise) ----------------
__global__ __launch_bounds__(256) void conv_split(
    const float* __restrict__ in, __nv_bfloat16* __restrict__ oh,
    __nv_bfloat16* __restrict__ ol, int n4)
{
    int i = blockIdx.x * 256 + threadIdx.x;
    if (i >= n4) return;
    float4 v = *(const float4*)(in + i * 4);
    __nv_bfloat16 h0 = __float2bfloat16(v.x), h1 = __float2bfloat16(v.y);
    __nv_bfloat16 h2 = __float2bfloat16(v.z), h3 = __float2bfloat16(v.w);
    __nv_bfloat162 hh0 = {h0, h1}, hh1 = {h2, h3};
    *(__nv_bfloat162*)(oh + i * 4)     = hh0;
    *(__nv_bfloat162*)(oh + i * 4 + 2) = hh1;
    __nv_bfloat162 ll0 = {__float2bfloat16(v.x - __bfloat162float(h0)),
                          __float2bfloat16(v.y - __bfloat162float(h1))};
    __nv_bfloat162 ll1 = {__float2bfloat16(v.z - __bfloat162float(h2)),
                          __float2bfloat16(v.w - __bfloat162float(h3))};
    *(__nv_bfloat162*)(ol + i * 4)     = ll0;
    *(__nv_bfloat162*)(ol + i * 4 + 2) = ll1;
}

// ---------------- WMMA bf16 split-K GEMM ----------------
#define ASTRIDE 48
#define BSTRIDE 80
__global__ __launch_bounds__(256) void gemm_wmma(
    const __nv_bfloat16* __restrict__ Ah, const __nv_bfloat16* __restrict__ Al,
    const __nv_bfloat16* __restrict__ Bh, const __nv_bfloat16* __restrict__ Bl,
    float* __restrict__ Part, int K, int N, int kz)
{
    __shared__ __nv_bfloat16 Ash[128][ASTRIDE], Asl[128][ASTRIDE];
    __shared__ __nv_bfloat16 Bsh[32][BSTRIDE],  Bsl[32][BSTRIDE];

    const int tid = threadIdx.x;
    const int n0  = blockIdx.x * 64;
    const int z   = blockIdx.z;
    const int w   = tid >> 5;
    const int wm  = (w & 3) * 32;
    const int wn  = (w >> 2) * 32;

    wmma::fragment<wmma::accumulator, 16, 16, 16, float> acc[2][2];
#pragma unroll
    for (int i = 0; i < 2; i++)
#pragma unroll
        for (int j = 0; j < 2; j++) wmma::fill_fragment(acc[i][j], 0.f);

    const int ar = tid >> 1, ac = (tid & 1) * 16;
    const int br = tid >> 3, bc = (tid & 7) * 8;

    const int kbeg = z * kz, kend = kbeg + kz;
    for (int k0 = kbeg; k0 < kend; k0 += 32) {
        {
            const __nv_bfloat16* pa = Ah + (size_t)ar * K + k0 + ac;
            const __nv_bfloat16* pl = Al + (size_t)ar * K + k0 + ac;
            *(uint4*)(&Ash[ar][ac])     = *(const uint4*)(pa);
            *(uint4*)(&Ash[ar][ac + 8]) = *(const uint4*)(pa + 8);
            *(uint4*)(&Asl[ar][ac])     = *(const uint4*)(pl);
            *(uint4*)(&Asl[ar][ac + 8]) = *(const uint4*)(pl + 8);
        }
        {
            const __nv_bfloat16* pb = Bh + (size_t)(k0 + br) * N + n0 + bc;
            const __nv_bfloat16* pl = Bl + (size_t)(k0 + br) * N + n0 + bc;
            *(uint4*)(&Bsh[br][bc]) = *(const uint4*)(pb);
            *(uint4*)(&Bsl[br][bc]) = *(const uint4*)(pl);
        }
        __syncthreads();

#pragma unroll
        for (int ks = 0; ks < 2; ks++) {
            wmma::fragment<wmma::matrix_a, 16, 16, 16, __nv_bfloat16, wmma::row_major> ah[2], al[2];
            wmma::fragment<wmma::matrix_b, 16, 16, 16, __nv_bfloat16, wmma::row_major> bh[2], bl[2];
#pragma unroll
            for (int i = 0; i < 2; i++) {
                wmma::load_matrix_sync(ah[i], &Ash[wm + i * 16][ks * 16], ASTRIDE);
                wmma::load_matrix_sync(al[i], &Asl[wm + i * 16][ks * 16], ASTRIDE);
            }
#pragma unroll
            for (int j = 0; j < 2; j++) {
                wmma::load_matrix_sync(bh[j], &Bsh[ks * 16][wn + j * 16], BSTRIDE);
                wmma::load_matrix_sync(bl[j], &Bsl[ks * 16][wn + j * 16], BSTRIDE);
            }
#pragma unroll
            for (int i = 0; i < 2; i++)
#pragma unroll
                for (int j = 0; j < 2; j++) {
                    wmma::mma_sync(acc[i][j], ah[i], bh[j], acc[i][j]);
                    wmma::mma_sync(acc[i][j], ah[i], bl[j], acc[i][j]);
                    wmma::mma_sync(acc[i][j], al[i], bh[j], acc[i][j]);
                }
        }
        __syncthreads();
    }

    float* dst = Part + (size_t)z * M_ * N;
#pragma unroll
    for (int i = 0; i < 2; i++)
#pragma unroll
        for (int j = 0; j < 2; j++)
            wmma::store_matrix_sync(dst + (size_t)(wm + i * 16) * N + n0 + wn + j * 16,
                                    acc[i][j], N, wmma::mem_row_major);
}

// ---------------- combine split-K partials + bias ----------------
__global__ __launch_bounds__(256) void combine_sk(
    const float* __restrict__ Part, const float* __restrict__ bias,
    float* __restrict__ Out, int MN, int N, int S)
{
    int i4 = blockIdx.x * 256 + threadIdx.x;
    int f = i4 * 4;
    if (f >= MN) return;
    float4 s = *(const float4*)(Part + f);
    for (int z = 1; z < S; z++) {
        float4 p = *(const float4*)(Part + (size_t)z * MN + f);
        s.x += p.x; s.y += p.y; s.z += p.z; s.w += p.w;
    }
    float4 bb = *(const float4*)(bias + (f % N));
    s.x += bb.x; s.y += bb.y; s.z += bb.z; s.w += bb.w;
    *(float4*)(Out + f) = s;
}

// ---------------- attention partials (flash-decoding) ----------------
__global__ __launch_bounds__(128) void attn_partial(
    const float* __restrict__ kc, const float* __restrict__ vc,
    const int* __restrict__ p_start, const int* __restrict__ p_causal)
{
    __shared__ float  Qs[T_][D_];
    __shared__ float  Ks[4][16][KSTRIDE];
    __shared__ float2 Ps[4][T_][32];

    const int tid  = threadIdx.x;
    const int w    = tid >> 5;
    const int lane = tid & 31;
    const int bh    = blockIdx.x >> 2;
    const int split = ((blockIdx.x & 3) << 2) | w;
    const int b = bh >> 4, h = bh & 15;

    const int start_pos = *p_start;
    const int causal    = *p_causal;
    const int S = start_pos + T_;
    const float QSCALE = 0.08838834764831845f * 1.4426950408889634f;

    for (int i = tid; i < T_ * 32; i += 128) {
        int t = i >> 5, dq = (i & 31) * 4;
        float4 v = *(const float4*)(g_qkv + (size_t)(b * T_ + t) * N3_ + h * D_ + dq);
        v.x *= QSCALE; v.y *= QSCALE; v.z *= QSCALE; v.w *= QSCALE;
        *(float4*)(&Qs[t][dq]) = v;
    }
    __syncthreads();

    unsigned long long acc[T_][2];
    float lacc[T_];
#pragma unroll
    for (int t = 0; t < T_; t++) { acc[t][0] = 0ull; acc[t][1] = 0ull; lacc[t] = 0.f; }

    const int s0 = split * CHUNK;
    const float* kbase = kc + (size_t)bh * MAXSEQ * D_;
    const float* vbase = vc + (size_t)bh * MAXSEQ * D_;
    const int key16 = lane & 15;
    const int dh    = lane >> 4;

    for (int tile = 0; tile < CHUNK / 32; tile++) {
        const int sb32 = s0 + tile * 32;

        for (int sub = 0; sub < 2; sub++) {
            const int sb = sb32 + sub * 16;
            // stage 16 K rows: full warp per row, 128 floats each
#pragma unroll 4
            for (int r = 0; r < 16; r++) {
                int s = sb + r;
                float4 kv = make_float4(0.f, 0.f, 0.f, 0.f);
                if (s < S) {
                    const float* krow = (s < start_pos)
                        ? (kbase + (size_t)s * D_)
                        : (g_qkv + (size_t)(b * T_ + (s - start_pos)) * N3_ + C_ + h * D_);
                    kv = *(const float4*)(krow + lane * 4);
                }
                *(float4*)(&Ks[w][r][lane * 4]) = kv;
            }
            __syncwarp();

            unsigned long long sc2[T_];
#pragma unroll
            for (int t = 0; t < T_; t++) sc2[t] = 0ull;
            const float* kp = &Ks[w][key16][dh * 64];
#pragma unroll 4
            for (int dq = 0; dq < 16; dq++) {
                ulonglong2 k2 = *(const ulonglong2*)(kp + dq * 4);
#pragma unroll
                for (int t = 0; t < T_; t++) {
                    ulonglong2 q2 = *(const ulonglong2*)(&Qs[t][dh * 64 + dq * 4]);
                    fma2(sc2[t], q2.x, k2.x);
                    fma2(sc2[t], q2.y, k2.y);
                }
            }
            const int s_key = sb + key16;
            const bool valid = (s_key < S);
#pragma unroll
            for (int t = 0; t < T_; t++) {
                float a, c; unpk(sc2[t], a, c);
                float v = a + c;
                v += __shfl_xor_sync(0xffffffffu, v, 16);
                float p = (valid && !(causal && s_key > t)) ? ex2(v) : 0.f;
                if (dh == 0) {
                    Ps[w][t][sub * 16 + key16] = make_float2(p, p);
                    lacc[t] += p;
                }
            }
            __syncwarp();
        }

#pragma unroll
        for (int jb = 0; jb < 4; jb++) {
            ulonglong2 vv[8];
#pragma unroll
            for (int u = 0; u < 8; u++) {
                int s = sb32 + jb * 8 + u;
                if (s < S) {
                    const float* vrow = (s < start_pos)
                        ? (vbase + (size_t)s * D_)
                        : (g_qkv + (size_t)(b * T_ + (s - start_pos)) * N3_ + 2 * C_ + h * D_);
                    vv[u] = *(const ulonglong2*)(vrow + lane * 4);
                } else { vv[u].x = 0ull; vv[u].y = 0ull; }
            }
#pragma unroll
            for (int u = 0; u < 8; u++) {
                int j = jb * 8 + u;
#pragma unroll
                for (int t = 0; t < T_; t++) {
                    unsigned long long p2 = *(const unsigned long long*)(&Ps[w][t][j]);
                    fma2(acc[t][0], p2, vv[u].x);
                    fma2(acc[t][1], p2, vv[u].y);
                }
            }
        }
        __syncwarp();
    }

    const int pbase = (bh * NS + split) * T_;
#pragma unroll
    for (int t = 0; t < T_; t++) {
        float4 o;
        unpk(acc[t][0], o.x, o.y);
        unpk(acc[t][1], o.z, o.w);
        *(float4*)(g_pacc + (size_t)(pbase + t) * D_ + lane * 4) = o;
        float l = lacc[t];
#pragma unroll
        for (int o2 = 16; o2; o2 >>= 1) l += __shfl_xor_sync(0xffffffffu, l, o2);
        if (lane == 0) g_pl[pbase + t] = l;
    }
}

// ---------------- combine attention splits ----------------
__global__ __launch_bounds__(128) void attn_combine()
{
    const int bht = blockIdx.x;
    const int bh = bht >> 3, t = bht & 7;
    const int d  = threadIdx.x;
    const int b = bh >> 4, h = bh & 15;
    float L = 0.f, y = 0.f;
#pragma unroll
    for (int si = 0; si < NS; si++) {
        L += g_pl[(bh * NS + si) * T_ + t];
        y += g_pacc[(size_t)((bh * NS + si) * T_ + t) * D_ + d];
    }
    g_y[(size_t)(b * T_ + t) * C_ + h * D_ + d] = (L > 0.f) ? (y / L) : 0.f;
}

// ---------------- launch ----------------
extern "C" void kernel_launch(void* const* d_in, const int* in_sizes, int n_in,
                              void* d_out, int out_size)
{
    const float* x      = (const float*)d_in[0];
    const float* kc     = (const float*)d_in[1];
    const float* vc     = (const float*)d_in[2];
    const float* w_attn = (const float*)d_in[3];
    const float* b_attn = (const float*)d_in[4];
    const float* w_proj = (const float*)d_in[5];
    const float* b_proj = (const float*)d_in[6];
    const int*   sp     = (const int*)d_in[7];
    const int*   ic     = (const int*)d_in[8];
    float* out = (float*)d_out;

    float *qkv, *y, *part;
    __nv_bfloat16 *xh, *xl, *yh, *yl, *wah, *wal, *wph, *wpl;
    cudaGetSymbolAddress((void**)&qkv,  g_qkv);
    cudaGetSymbolAddress((void**)&y,    g_y);
    cudaGetSymbolAddress((void**)&part, g_part);
    cudaGetSymbolAddress((void**)&xh,  g_xh);  cudaGetSymbolAddress((void**)&xl, g_xl);
    cudaGetSymbolAddress((void**)&yh,  g_yh);  cudaGetSymbolAddress((void**)&yl, g_yl);
    cudaGetSymbolAddress((void**)&wah, g_wah); cudaGetSymbolAddress((void**)&wal, g_wal);
    cudaGetSymbolAddress((void**)&wph, g_wph); cudaGetSymbolAddress((void**)&wpl, g_wpl);

    // hi/lo splits
    conv_split<<<(M_ * C_ / 4) / 256, 256>>>(x, xh, xl, M_ * C_ / 4);
    conv_split<<<(C_ * N3_ / 4) / 256, 256>>>(w_attn, wah, wal, C_ * N3_ / 4);
    conv_split<<<(C_ * C_ / 4) / 256, 256>>>(w_proj, wph, wpl, C_ * C_ / 4);

    // QKV projection (tensor cores, split-K=2)
    gemm_wmma<<<dim3(N3_ / 64, 1, 2), 256>>>(xh, xl, wah, wal, part, C_, N3_, C_ / 2);
    combine_sk<<<(M_ * N3_ / 4) / 256, 256>>>(part, b_attn, qkv, M_ * N3_, N3_, 2);

    // attention
    attn_partial<<<B_ * H_ * 4, 128>>>(kc, vc, sp, ic);
    attn_combine<<<B_ * H_ * T_, 128>>>();

    // output projection (split-K=4)
    conv_split<<<(M_ * C_ / 4) / 256, 256>>>(y, yh, yl, M_ * C_ / 4);
    gemm_wmma<<<dim3(C_ / 64, 1, 4), 256>>>(yh, yl, wph, wpl, part, C_, C_, C_ / 4);
    combine_sk<<<(M_ * C_ / 4) / 256, 256>>>(part, b_proj, out, M_ * C_, C_, 4);
}

// round 9
// speedup vs baseline: 1.2906x; 1.0269x over previous
#include <cuda_runtime.h>
#include <cuda_bf16.h>
#include <mma.h>
#include <math.h>
#include <stdint.h>

using namespace nvcuda;

#define B_   16
#define T_   8
#define C_   2048
#define H_   16
#define D_   128
#define MAXSEQ 4096
#define M_   (B_*T_)      // 128
#define N3_  (3*C_)       // 6144
#define NS   16
#define CHUNK (MAXSEQ/NS) // 256

// ---------------- scratch ----------------
__device__ __align__(16) float g_qkv[M_ * N3_];
__device__ __align__(16) float g_part[4 * M_ * N3_];
__device__ __align__(16) float g_pacc[B_*H_ * NS * T_ * D_];
__device__               float g_pl[B_*H_ * NS * T_];
__device__ __align__(16) float g_y[M_ * C_];

// ---------------- helpers ----------------
__device__ __forceinline__ void fma2(unsigned long long& d,
                                     unsigned long long a,
                                     unsigned long long b) {
    asm("fma.rn.f32x2 %0, %1, %2, %0;" : "+l"(d) : "l"(a), "l"(b));
}
__device__ __forceinline__ void unpk(unsigned long long d, float& x, float& y) {
    asm("mov.b64 {%0, %1}, %2;" : "=f"(x), "=f"(y) : "l"(d));
}
__device__ __forceinline__ float ex2(float x) {
    float r; asm("ex2.approx.f32 %0, %1;" : "=f"(r) : "f"(x)); return r;
}
__device__ __forceinline__ uint4 pack_hi(float4 a, float4 b) {
    union { __nv_bfloat162 h[4]; uint4 u; } r;
    r.h[0] = __floats2bfloat162_rn(a.x, a.y);
    r.h[1] = __floats2bfloat162_rn(a.z, a.w);
    r.h[2] = __floats2bfloat162_rn(b.x, b.y);
    r.h[3] = __floats2bfloat162_rn(b.z, b.w);
    return r.u;
}
__device__ __forceinline__ uint4 pack_lo(float4 a, float4 b, uint4 hu) {
    union { __nv_bfloat162 h[4]; uint4 u; } hh; hh.u = hu;
    union { __nv_bfloat162 h[4]; uint4 u; } r;
    float2 f0 = __bfloat1622float2(hh.h[0]);
    float2 f1 = __bfloat1622float2(hh.h[1]);
    float2 f2 = __bfloat1622float2(hh.h[2]);
    float2 f3 = __bfloat1622float2(hh.h[3]);
    r.h[0] = __floats2bfloat162_rn(a.x - f0.x, a.y - f0.y);
    r.h[1] = __floats2bfloat162_rn(a.z - f1.x, a.w - f1.y);
    r.h[2] = __floats2bfloat162_rn(b.x - f2.x, b.y - f2.y);
    r.h[3] = __floats2bfloat162_rn(b.z - f3.x, b.w - f3.y);
    return r.u;
}

// ---------------- fused-convert, pipelined WMMA split-K GEMM ----------------
// Part[z,128,N] = A_f32[128,K_z] @ B_f32[K_z,N] via 3-term bf16 hi/lo.
#define ASTRIDE 48
#define BSTRIDE 80
__global__ __launch_bounds__(256) void gemm_f32(
    const float* __restrict__ A, const float* __restrict__ Bm,
    float* __restrict__ Part, int K, int N, int kz)
{
    __shared__ __nv_bfloat16 Ash[128][ASTRIDE], Asl[128][ASTRIDE];
    __shared__ __nv_bfloat16 Bsh[32][BSTRIDE],  Bsl[32][BSTRIDE];

    const int tid = threadIdx.x;
    const int n0  = blockIdx.x * 64;
    const int z   = blockIdx.z;
    const int w   = tid >> 5;
    const int wm  = (w & 3) * 32;
    const int wn  = (w >> 2) * 32;

    wmma::fragment<wmma::accumulator, 16, 16, 16, float> acc[2][2];
#pragma unroll
    for (int i = 0; i < 2; i++)
#pragma unroll
        for (int j = 0; j < 2; j++) wmma::fill_fragment(acc[i][j], 0.f);

    const int ar = tid >> 1, ac = (tid & 1) * 16;
    const int br = tid >> 3, bc = (tid & 7) * 8;
    const int kbeg = z * kz, kend = kbeg + kz;

    float4 a0, a1, a2, a3, b0, b1;
    {
        const float* pa = A + (size_t)ar * K + kbeg + ac;
        a0 = *(const float4*)(pa);     a1 = *(const float4*)(pa + 4);
        a2 = *(const float4*)(pa + 8); a3 = *(const float4*)(pa + 12);
        const float* pb = Bm + (size_t)(kbeg + br) * N + n0 + bc;
        b0 = *(const float4*)(pb);     b1 = *(const float4*)(pb + 4);
    }

    for (int k0 = kbeg; k0 < kend; k0 += 32) {
        // convert + store current chunk
        {
            uint4 h;
            h = pack_hi(a0, a1);
            *(uint4*)(&Ash[ar][ac])     = h; *(uint4*)(&Asl[ar][ac])     = pack_lo(a0, a1, h);
            h = pack_hi(a2, a3);
            *(uint4*)(&Ash[ar][ac + 8]) = h; *(uint4*)(&Asl[ar][ac + 8]) = pack_lo(a2, a3, h);
            h = pack_hi(b0, b1);
            *(uint4*)(&Bsh[br][bc])     = h; *(uint4*)(&Bsl[br][bc])     = pack_lo(b0, b1, h);
        }
        __syncthreads();
        // prefetch next chunk (overlaps with MMA below)
        if (k0 + 32 < kend) {
            const float* pa = A + (size_t)ar * K + (k0 + 32) + ac;
            a0 = *(const float4*)(pa);     a1 = *(const float4*)(pa + 4);
            a2 = *(const float4*)(pa + 8); a3 = *(const float4*)(pa + 12);
            const float* pb = Bm + (size_t)(k0 + 32 + br) * N + n0 + bc;
            b0 = *(const float4*)(pb);     b1 = *(const float4*)(pb + 4);
        }
#pragma unroll
        for (int ks = 0; ks < 2; ks++) {
            wmma::fragment<wmma::matrix_a, 16, 16, 16, __nv_bfloat16, wmma::row_major> ah[2], al[2];
            wmma::fragment<wmma::matrix_b, 16, 16, 16, __nv_bfloat16, wmma::row_major> bh[2], bl[2];
#pragma unroll
            for (int i = 0; i < 2; i++) {
                wmma::load_matrix_sync(ah[i], &Ash[wm + i * 16][ks * 16], ASTRIDE);
                wmma::load_matrix_sync(al[i], &Asl[wm + i * 16][ks * 16], ASTRIDE);
            }
#pragma unroll
            for (int j = 0; j < 2; j++) {
                wmma::load_matrix_sync(bh[j], &Bsh[ks * 16][wn + j * 16], BSTRIDE);
                wmma::load_matrix_sync(bl[j], &Bsl[ks * 16][wn + j * 16], BSTRIDE);
            }
#pragma unroll
            for (int i = 0; i < 2; i++)
#pragma unroll
                for (int j = 0; j < 2; j++) {
                    wmma::mma_sync(acc[i][j], ah[i], bh[j], acc[i][j]);
                    wmma::mma_sync(acc[i][j], ah[i], bl[j], acc[i][j]);
                    wmma::mma_sync(acc[i][j], al[i], bh[j], acc[i][j]);
                }
        }
        __syncthreads();
    }

    float* dst = Part + (size_t)z * M_ * N;
#pragma unroll
    for (int i = 0; i < 2; i++)
#pragma unroll
        for (int j = 0; j < 2; j++)
            wmma::store_matrix_sync(dst + (size_t)(wm + i * 16) * N + n0 + wn + j * 16,
                                    acc[i][j], N, wmma::mem_row_major);
}

// ---------------- combine split-K partials + bias ----------------
__global__ __launch_bounds__(256) void combine_sk(
    const float* __restrict__ Part, const float* __restrict__ bias,
    float* __restrict__ Out, int MN, int N, int S)
{
    int i4 = blockIdx.x * 256 + threadIdx.x;
    int f = i4 * 4;
    if (f >= MN) return;
    float4 s = *(const float4*)(Part + f);
    for (int z = 1; z < S; z++) {
        float4 p = *(const float4*)(Part + (size_t)z * MN + f);
        s.x += p.x; s.y += p.y; s.z += p.z; s.w += p.w;
    }
    float4 bb = *(const float4*)(bias + (f % N));
    s.x += bb.x; s.y += bb.y; s.z += bb.z; s.w += bb.w;
    *(float4*)(Out + f) = s;
}

// ---------------- attention partials (flash-decoding, swizzled Ks) --------
__global__ __launch_bounds__(128) void attn_partial(
    const float* __restrict__ kc, const float* __restrict__ vc,
    const int* __restrict__ p_start, const int* __restrict__ p_causal)
{
    __shared__ float  Qs[T_][D_];        // 4 KB
    __shared__ float  Ks[4][16][128];    // 32 KB, XOR-swizzled columns
    __shared__ float2 Ps[4][T_][32];     // 8 KB

    const int tid  = threadIdx.x;
    const int w    = tid >> 5;
    const int lane = tid & 31;
    const int bh    = blockIdx.x >> 2;
    const int split = ((blockIdx.x & 3) << 2) | w;
    const int b = bh >> 4, h = bh & 15;

    const int start_pos = *p_start;
    const int causal    = *p_causal;
    const int S = start_pos + T_;
    const float QSCALE = 0.08838834764831845f * 1.4426950408889634f;

    for (int i = tid; i < T_ * 32; i += 128) {
        int t = i >> 5, dq = (i & 31) * 4;
        float4 v = *(const float4*)(g_qkv + (size_t)(b * T_ + t) * N3_ + h * D_ + dq);
        v.x *= QSCALE; v.y *= QSCALE; v.z *= QSCALE; v.w *= QSCALE;
        *(float4*)(&Qs[t][dq]) = v;
    }
    __syncthreads();

    unsigned long long acc[T_][2];
    float lacc[T_];
#pragma unroll
    for (int t = 0; t < T_; t++) { acc[t][0] = 0ull; acc[t][1] = 0ull; lacc[t] = 0.f; }

    const int s0 = split * CHUNK;
    const float* kbase = kc + (size_t)bh * MAXSEQ * D_;
    const float* vbase = vc + (size_t)bh * MAXSEQ * D_;
    const int key16 = lane & 15;
    const int dh    = lane >> 4;
    const int kx    = key16 & 7;

    for (int tile = 0; tile < CHUNK / 32; tile++) {
        const int sb32 = s0 + tile * 32;

        for (int sub = 0; sub < 2; sub++) {
            const int sb = sb32 + sub * 16;
            // stage 16 K rows, XOR-swizzled columns (conflict-free STS)
#pragma unroll 4
            for (int r = 0; r < 16; r++) {
                int s = sb + r;
                float4 kv = make_float4(0.f, 0.f, 0.f, 0.f);
                if (s < S) {
                    const float* krow = (s < start_pos)
                        ? (kbase + (size_t)s * D_)
                        : (g_qkv + (size_t)(b * T_ + (s - start_pos)) * N3_ + C_ + h * D_);
                    kv = *(const float4*)(krow + lane * 4);
                }
                int c = lane ^ (r & 7);
                *(float4*)(&Ks[w][r][c * 4]) = kv;
            }
            __syncwarp();

            // scores: lane = (key, d-half); conflict-free LDS via same swizzle
            unsigned long long sc2[T_];
#pragma unroll
            for (int t = 0; t < T_; t++) sc2[t] = 0ull;
            const float* kp = &Ks[w][key16][0];
#pragma unroll 4
            for (int dq = 0; dq < 16; dq++) {
                int v = dh * 16 + dq;
                int c = v ^ kx;
                ulonglong2 k2 = *(const ulonglong2*)(kp + c * 4);
#pragma unroll
                for (int t = 0; t < T_; t++) {
                    ulonglong2 q2 = *(const ulonglong2*)(&Qs[t][v * 4]);
                    fma2(sc2[t], q2.x, k2.x);
                    fma2(sc2[t], q2.y, k2.y);
                }
            }
            const int s_key = sb + key16;
            const bool valid = (s_key < S);
#pragma unroll
            for (int t = 0; t < T_; t++) {
                float a, c; unpk(sc2[t], a, c);
                float v = a + c;
                v += __shfl_xor_sync(0xffffffffu, v, 16);
                float p = (valid && !(causal && s_key > t)) ? ex2(v) : 0.f;
                if (dh == 0) {
                    Ps[w][t][sub * 16 + key16] = make_float2(p, p);
                    lacc[t] += p;
                }
            }
            __syncwarp();
        }

        // P @ V over the 32-key tile; lane owns 4 dims
#pragma unroll
        for (int jb = 0; jb < 4; jb++) {
            ulonglong2 vv[8];
#pragma unroll
            for (int u = 0; u < 8; u++) {
                int s = sb32 + jb * 8 + u;
                if (s < S) {
                    const float* vrow = (s < start_pos)
                        ? (vbase + (size_t)s * D_)
                        : (g_qkv + (size_t)(b * T_ + (s - start_pos)) * N3_ + 2 * C_ + h * D_);
                    vv[u] = *(const ulonglong2*)(vrow + lane * 4);
                } else { vv[u].x = 0ull; vv[u].y = 0ull; }
            }
#pragma unroll
            for (int u = 0; u < 8; u++) {
                int j = jb * 8 + u;
#pragma unroll
                for (int t = 0; t < T_; t++) {
                    unsigned long long p2 = *(const unsigned long long*)(&Ps[w][t][j]);
                    fma2(acc[t][0], p2, vv[u].x);
                    fma2(acc[t][1], p2, vv[u].y);
                }
            }
        }
        __syncwarp();
    }

    const int pbase = (bh * NS + split) * T_;
#pragma unroll
    for (int t = 0; t < T_; t++) {
        float4 o;
        unpk(acc[t][0], o.x, o.y);
        unpk(acc[t][1], o.z, o.w);
        *(float4*)(g_pacc + (size_t)(pbase + t) * D_ + lane * 4) = o;
        float l = lacc[t];
#pragma unroll
        for (int o2 = 16; o2; o2 >>= 1) l += __shfl_xor_sync(0xffffffffu, l, o2);
        if (lane == 0) g_pl[pbase + t] = l;
    }
}

// ---------------- combine attention splits ----------------
__global__ __launch_bounds__(128) void attn_combine()
{
    const int bht = blockIdx.x;
    const int bh = bht >> 3, t = bht & 7;
    const int d  = threadIdx.x;
    const int b = bh >> 4, h = bh & 15;
    float L = 0.f, y = 0.f;
#pragma unroll
    for (int si = 0; si < NS; si++) {
        L += g_pl[(bh * NS + si) * T_ + t];
        y += g_pacc[(size_t)((bh * NS + si) * T_ + t) * D_ + d];
    }
    g_y[(size_t)(b * T_ + t) * C_ + h * D_ + d] = (L > 0.f) ? (y / L) : 0.f;
}

// ---------------- launch ----------------
extern "C" void kernel_launch(void* const* d_in, const int* in_sizes, int n_in,
                              void* d_out, int out_size)
{
    const float* x      = (const float*)d_in[0];
    const float* kc     = (const float*)d_in[1];
    const float* vc     = (const float*)d_in[2];
    const float* w_attn = (const float*)d_in[3];
    const float* b_attn = (const float*)d_in[4];
    const float* w_proj = (const float*)d_in[5];
    const float* b_proj = (const float*)d_in[6];
    const int*   sp     = (const int*)d_in[7];
    const int*   ic     = (const int*)d_in[8];
    float* out = (float*)d_out;

    float *qkv, *y, *part;
    cudaGetSymbolAddress((void**)&qkv,  g_qkv);
    cudaGetSymbolAddress((void**)&y,    g_y);
    cudaGetSymbolAddress((void**)&part, g_part);

    // QKV projection (fused convert, split-K=4)
    gemm_f32<<<dim3(N3_ / 64, 1, 4), 256>>>(x, w_attn, part, C_, N3_, C_ / 4);
    combine_sk<<<(M_ * N3_ / 4) / 256, 256>>>(part, b_attn, qkv, M_ * N3_, N3_, 4);

    // attention
    attn_partial<<<B_ * H_ * 4, 128>>>(kc, vc, sp, ic);
    attn_combine<<<B_ * H_ * T_, 128>>>();

    // output projection (fused convert, split-K=8)
    gemm_f32<<<dim3(C_ / 64, 1, 8), 256>>>(y, w_proj, part, C_, C_, C_ / 8);
    combine_sk<<<(M_ * C_ / 4) / 256, 256>>>(part, b_proj, out, M_ * C_, C_, 8);
}

// round 10
// speedup vs baseline: 1.9834x; 1.5368x over previous
#include <cuda_runtime.h>
#include <cuda_bf16.h>
#include <mma.h>
#include <math.h>
#include <stdint.h>

using namespace nvcuda;

#define B_   16
#define T_   8
#define C_   2048
#define H_   16
#define D_   128
#define MAXSEQ 4096
#define M_   (B_*T_)      // 128
#define N3_  (3*C_)       // 6144
#define NS   16
#define CHUNK (MAXSEQ/NS) // 256
#define STG  16           // keys per pipeline stage
#define NSTG (CHUNK/STG)  // 16

// ---------------- scratch ----------------
__device__ __align__(16) float g_qkv[M_ * N3_];
__device__ __align__(16) float g_part[4 * M_ * N3_];
__device__ __align__(16) float g_pacc[B_*H_ * NS * T_ * D_];
__device__               float g_pl[B_*H_ * NS * T_];
__device__ __align__(16) float g_y[M_ * C_];

// ---------------- helpers ----------------
__device__ __forceinline__ void fma2(unsigned long long& d,
                                     unsigned long long a,
                                     unsigned long long b) {
    asm("fma.rn.f32x2 %0, %1, %2, %0;" : "+l"(d) : "l"(a), "l"(b));
}
__device__ __forceinline__ void unpk(unsigned long long d, float& x, float& y) {
    asm("mov.b64 {%0, %1}, %2;" : "=f"(x), "=f"(y) : "l"(d));
}
__device__ __forceinline__ float ex2(float x) {
    float r; asm("ex2.approx.f32 %0, %1;" : "=f"(r) : "f"(x)); return r;
}
__device__ __forceinline__ uint32_t smem_u32(const void* p) {
    uint32_t a;
    asm("{ .reg .u64 t; cvta.to.shared.u64 t, %1; cvt.u32.u64 %0, t; }"
        : "=r"(a) : "l"(p));
    return a;
}
__device__ __forceinline__ uint4 pack_hi(float4 a, float4 b) {
    union { __nv_bfloat162 h[4]; uint4 u; } r;
    r.h[0] = __floats2bfloat162_rn(a.x, a.y);
    r.h[1] = __floats2bfloat162_rn(a.z, a.w);
    r.h[2] = __floats2bfloat162_rn(b.x, b.y);
    r.h[3] = __floats2bfloat162_rn(b.z, b.w);
    return r.u;
}
__device__ __forceinline__ uint4 pack_lo(float4 a, float4 b, uint4 hu) {
    union { __nv_bfloat162 h[4]; uint4 u; } hh; hh.u = hu;
    union { __nv_bfloat162 h[4]; uint4 u; } r;
    float2 f0 = __bfloat1622float2(hh.h[0]);
    float2 f1 = __bfloat1622float2(hh.h[1]);
    float2 f2 = __bfloat1622float2(hh.h[2]);
    float2 f3 = __bfloat1622float2(hh.h[3]);
    r.h[0] = __floats2bfloat162_rn(a.x - f0.x, a.y - f0.y);
    r.h[1] = __floats2bfloat162_rn(a.z - f1.x, a.w - f1.y);
    r.h[2] = __floats2bfloat162_rn(b.x - f2.x, b.y - f2.y);
    r.h[3] = __floats2bfloat162_rn(b.z - f3.x, b.w - f3.y);
    return r.u;
}

// ---------------- fused-convert, pipelined WMMA split-K GEMM ----------------
#define ASTRIDE 48
#define BSTRIDE 80
__global__ __launch_bounds__(256) void gemm_f32(
    const float* __restrict__ A, const float* __restrict__ Bm,
    float* __restrict__ Part, int K, int N, int kz)
{
    __shared__ __nv_bfloat16 Ash[128][ASTRIDE], Asl[128][ASTRIDE];
    __shared__ __nv_bfloat16 Bsh[32][BSTRIDE],  Bsl[32][BSTRIDE];

    const int tid = threadIdx.x;
    const int n0  = blockIdx.x * 64;
    const int z   = blockIdx.z;
    const int w   = tid >> 5;
    const int wm  = (w & 3) * 32;
    const int wn  = (w >> 2) * 32;

    wmma::fragment<wmma::accumulator, 16, 16, 16, float> acc[2][2];
#pragma unroll
    for (int i = 0; i < 2; i++)
#pragma unroll
        for (int j = 0; j < 2; j++) wmma::fill_fragment(acc[i][j], 0.f);

    const int ar = tid >> 1, ac = (tid & 1) * 16;
    const int br = tid >> 3, bc = (tid & 7) * 8;
    const int kbeg = z * kz, kend = kbeg + kz;

    float4 a0, a1, a2, a3, b0, b1;
    {
        const float* pa = A + (size_t)ar * K + kbeg + ac;
        a0 = *(const float4*)(pa);     a1 = *(const float4*)(pa + 4);
        a2 = *(const float4*)(pa + 8); a3 = *(const float4*)(pa + 12);
        const float* pb = Bm + (size_t)(kbeg + br) * N + n0 + bc;
        b0 = *(const float4*)(pb);     b1 = *(const float4*)(pb + 4);
    }

    for (int k0 = kbeg; k0 < kend; k0 += 32) {
        {
            uint4 h;
            h = pack_hi(a0, a1);
            *(uint4*)(&Ash[ar][ac])     = h; *(uint4*)(&Asl[ar][ac])     = pack_lo(a0, a1, h);
            h = pack_hi(a2, a3);
            *(uint4*)(&Ash[ar][ac + 8]) = h; *(uint4*)(&Asl[ar][ac + 8]) = pack_lo(a2, a3, h);
            h = pack_hi(b0, b1);
            *(uint4*)(&Bsh[br][bc])     = h; *(uint4*)(&Bsl[br][bc])     = pack_lo(b0, b1, h);
        }
        __syncthreads();
        if (k0 + 32 < kend) {
            const float* pa = A + (size_t)ar * K + (k0 + 32) + ac;
            a0 = *(const float4*)(pa);     a1 = *(const float4*)(pa + 4);
            a2 = *(const float4*)(pa + 8); a3 = *(const float4*)(pa + 12);
            const float* pb = Bm + (size_t)(k0 + 32 + br) * N + n0 + bc;
            b0 = *(const float4*)(pb);     b1 = *(const float4*)(pb + 4);
        }
#pragma unroll
        for (int ks = 0; ks < 2; ks++) {
            wmma::fragment<wmma::matrix_a, 16, 16, 16, __nv_bfloat16, wmma::row_major> ah[2], al[2];
            wmma::fragment<wmma::matrix_b, 16, 16, 16, __nv_bfloat16, wmma::row_major> bh[2], bl[2];
#pragma unroll
            for (int i = 0; i < 2; i++) {
                wmma::load_matrix_sync(ah[i], &Ash[wm + i * 16][ks * 16], ASTRIDE);
                wmma::load_matrix_sync(al[i], &Asl[wm + i * 16][ks * 16], ASTRIDE);
            }
#pragma unroll
            for (int j = 0; j < 2; j++) {
                wmma::load_matrix_sync(bh[j], &Bsh[ks * 16][wn + j * 16], BSTRIDE);
                wmma::load_matrix_sync(bl[j], &Bsl[ks * 16][wn + j * 16], BSTRIDE);
            }
#pragma unroll
            for (int i = 0; i < 2; i++)
#pragma unroll
                for (int j = 0; j < 2; j++) {
                    wmma::mma_sync(acc[i][j], ah[i], bh[j], acc[i][j]);
                    wmma::mma_sync(acc[i][j], ah[i], bl[j], acc[i][j]);
                    wmma::mma_sync(acc[i][j], al[i], bh[j], acc[i][j]);
                }
        }
        __syncthreads();
    }

    float* dst = Part + (size_t)z * M_ * N;
#pragma unroll
    for (int i = 0; i < 2; i++)
#pragma unroll
        for (int j = 0; j < 2; j++)
            wmma::store_matrix_sync(dst + (size_t)(wm + i * 16) * N + n0 + wn + j * 16,
                                    acc[i][j], N, wmma::mem_row_major);
}

// ---------------- combine split-K partials + bias ----------------
__global__ __launch_bounds__(256) void combine_sk(
    const float* __restrict__ Part, const float* __restrict__ bias,
    float* __restrict__ Out, int MN, int N, int S)
{
    int i4 = blockIdx.x * 256 + threadIdx.x;
    int f = i4 * 4;
    if (f >= MN) return;
    float4 s = *(const float4*)(Part + f);
    for (int z = 1; z < S; z++) {
        float4 p = *(const float4*)(Part + (size_t)z * MN + f);
        s.x += p.x; s.y += p.y; s.z += p.z; s.w += p.w;
    }
    float4 bb = *(const float4*)(bias + (f % N));
    s.x += bb.x; s.y += bb.y; s.z += bb.z; s.w += bb.w;
    *(float4*)(Out + f) = s;
}

// ---------------- attention partials: cp.async pipelined flash-decoding ----
// dyn smem: Qs[8][128] | Ks[4][2][16][128] | Ps[4][8][16] float2  = 72KB
#define ATTN_SMEM (4096 + 4*2*16*128*4 + 4*8*16*8)

__global__ __launch_bounds__(128) void attn_partial(
    const float* __restrict__ kc, const float* __restrict__ vc,
    const int* __restrict__ p_start, const int* __restrict__ p_causal)
{
    extern __shared__ __align__(16) char smraw[];
    float*  Qs = (float*)smraw;                       // 1024 floats
    float*  Ks = Qs + T_ * D_;                        // 4*2*16*128 floats
    float2* Ps = (float2*)(Ks + 4 * 2 * 16 * 128);    // [4][8][16]

    const int tid  = threadIdx.x;
    const int w    = tid >> 5;
    const int lane = tid & 31;
    const int bh    = blockIdx.x >> 2;
    const int split = ((blockIdx.x & 3) << 2) | w;
    const int b = bh >> 4, h = bh & 15;

    const int start_pos = *p_start;
    const int causal    = *p_causal;
    const int S = start_pos + T_;
    const float QSCALE = 0.08838834764831845f * 1.4426950408889634f;

    for (int i = tid; i < T_ * 32; i += 128) {
        int t = i >> 5, dq = (i & 31) * 4;
        float4 v = *(const float4*)(g_qkv + (size_t)(b * T_ + t) * N3_ + h * D_ + dq);
        v.x *= QSCALE; v.y *= QSCALE; v.z *= QSCALE; v.w *= QSCALE;
        *(float4*)(&Qs[t * D_ + dq]) = v;
    }
    __syncthreads();

    unsigned long long acc[T_][2];
    float lacc[T_];
#pragma unroll
    for (int t = 0; t < T_; t++) { acc[t][0] = 0ull; acc[t][1] = 0ull; lacc[t] = 0.f; }

    const int s0 = split * CHUNK;
    const float* kbase = kc + (size_t)bh * MAXSEQ * D_;
    const float* vbase = vc + (size_t)bh * MAXSEQ * D_;
    const float* kqkv  = g_qkv + (size_t)(b * T_) * N3_ + C_ + h * D_;
    const float* vqkv  = g_qkv + (size_t)(b * T_) * N3_ + 2 * C_ + h * D_;
    const int key16 = lane & 15;
    const int dh    = lane >> 4;
    const int kx    = key16 & 7;

    float* kwarp = Ks + (size_t)w * 2 * 16 * 128;

    // issue one stage of K cp.asyncs into buf
    auto issueK = [&](int st, int buf) {
        const int sb = s0 + st * STG;
        float* kbuf = kwarp + buf * 16 * 128;
#pragma unroll
        for (int r = 0; r < STG; r++) {
            int s = sb + r; if (s >= S) s = S - 1;
            const float* krow = (s < start_pos)
                ? (kbase + (size_t)s * D_)
                : (kqkv + (size_t)(s - start_pos) * N3_);
            uint32_t dst = smem_u32(kbuf + r * 128 + ((lane ^ (r & 7)) * 4));
            asm volatile("cp.async.cg.shared.global [%0], [%1], 16;"
                         :: "r"(dst), "l"(krow + lane * 4) : "memory");
        }
        asm volatile("cp.async.commit_group;" ::: "memory");
    };

    issueK(0, 0);
    issueK(1, 1);

    for (int st = 0; st < NSTG; st++) {
        const int sb  = s0 + st * STG;
        const int buf = st & 1;

        if (st == NSTG - 1)
            asm volatile("cp.async.wait_group 0;" ::: "memory");
        else
            asm volatile("cp.async.wait_group 1;" ::: "memory");
        __syncwarp();

        // prefetch V rows for this stage (16 LDG.128 in flight over score phase)
        ulonglong2 vv[STG];
#pragma unroll
        for (int u = 0; u < STG; u++) {
            int s = sb + u; if (s >= S) s = S - 1;
            const float* vrow = (s < start_pos)
                ? (vbase + (size_t)s * D_)
                : (vqkv + (size_t)(s - start_pos) * N3_);
            vv[u] = *(const ulonglong2*)(vrow + lane * 4);
        }

        // scores: lane = (key16, dh half)
        unsigned long long sc2[T_];
#pragma unroll
        for (int t = 0; t < T_; t++) sc2[t] = 0ull;
        const float* kp = kwarp + buf * 16 * 128 + key16 * 128;
#pragma unroll 4
        for (int dq = 0; dq < 16; dq++) {
            int v = dh * 16 + dq;
            int c = v ^ kx;
            ulonglong2 k2 = *(const ulonglong2*)(kp + c * 4);
#pragma unroll
            for (int t = 0; t < T_; t++) {
                ulonglong2 q2 = *(const ulonglong2*)(&Qs[t * D_ + v * 4]);
                fma2(sc2[t], q2.x, k2.x);
                fma2(sc2[t], q2.y, k2.y);
            }
        }
        const int s_key = sb + key16;
        const bool valid = (s_key < S);
#pragma unroll
        for (int t = 0; t < T_; t++) {
            float a, c; unpk(sc2[t], a, c);
            float v = a + c;
            v += __shfl_xor_sync(0xffffffffu, v, 16);
            float p = (valid && !(causal && s_key > t)) ? ex2(v) : 0.f;
            if (dh == 0) {
                Ps[(w * T_ + t) * 16 + key16] = make_float2(p, p);
                lacc[t] += p;
            }
        }
        __syncwarp();

        // P @ V: lane owns 4 dims
#pragma unroll
        for (int u = 0; u < STG; u++) {
#pragma unroll
            for (int t = 0; t < T_; t++) {
                unsigned long long p2 =
                    *(const unsigned long long*)(&Ps[(w * T_ + t) * 16 + u]);
                fma2(acc[t][0], p2, vv[u].x);
                fma2(acc[t][1], p2, vv[u].y);
            }
        }
        __syncwarp();

        if (st + 2 < NSTG) issueK(st + 2, buf);
    }

    const int pbase = (bh * NS + split) * T_;
#pragma unroll
    for (int t = 0; t < T_; t++) {
        float4 o;
        unpk(acc[t][0], o.x, o.y);
        unpk(acc[t][1], o.z, o.w);
        *(float4*)(g_pacc + (size_t)(pbase + t) * D_ + lane * 4) = o;
        float l = lacc[t];
#pragma unroll
        for (int o2 = 16; o2; o2 >>= 1) l += __shfl_xor_sync(0xffffffffu, l, o2);
        if (lane == 0) g_pl[pbase + t] = l;
    }
}

// ---------------- combine attention splits ----------------
__global__ __launch_bounds__(128) void attn_combine()
{
    const int bht = blockIdx.x;
    const int bh = bht >> 3, t = bht & 7;
    const int d  = threadIdx.x;
    const int b = bh >> 4, h = bh & 15;
    float L = 0.f, y = 0.f;
#pragma unroll
    for (int si = 0; si < NS; si++) {
        L += g_pl[(bh * NS + si) * T_ + t];
        y += g_pacc[(size_t)((bh * NS + si) * T_ + t) * D_ + d];
    }
    g_y[(size_t)(b * T_ + t) * C_ + h * D_ + d] = (L > 0.f) ? (y / L) : 0.f;
}

// ---------------- launch ----------------
extern "C" void kernel_launch(void* const* d_in, const int* in_sizes, int n_in,
                              void* d_out, int out_size)
{
    const float* x      = (const float*)d_in[0];
    const float* kc     = (const float*)d_in[1];
    const float* vc     = (const float*)d_in[2];
    const float* w_attn = (const float*)d_in[3];
    const float* b_attn = (const float*)d_in[4];
    const float* w_proj = (const float*)d_in[5];
    const float* b_proj = (const float*)d_in[6];
    const int*   sp     = (const int*)d_in[7];
    const int*   ic     = (const int*)d_in[8];
    float* out = (float*)d_out;

    static bool attr = false;
    if (!attr) {
        cudaFuncSetAttribute(attn_partial,
                             cudaFuncAttributeMaxDynamicSharedMemorySize, ATTN_SMEM);
        attr = true;
    }

    float *qkv, *y, *part;
    cudaGetSymbolAddress((void**)&qkv,  g_qkv);
    cudaGetSymbolAddress((void**)&y,    g_y);
    cudaGetSymbolAddress((void**)&part, g_part);

    // QKV projection (fused convert, split-K=4)
    gemm_f32<<<dim3(N3_ / 64, 1, 4), 256>>>(x, w_attn, part, C_, N3_, C_ / 4);
    combine_sk<<<(M_ * N3_ / 4) / 256, 256>>>(part, b_attn, qkv, M_ * N3_, N3_, 4);

    // attention
    attn_partial<<<B_ * H_ * 4, 128, ATTN_SMEM>>>(kc, vc, sp, ic);
    attn_combine<<<B_ * H_ * T_, 128>>>();

    // output projection (fused convert, split-K=8)
    gemm_f32<<<dim3(C_ / 64, 1, 8), 256>>>(y, w_proj, part, C_, C_, C_ / 8);
    combine_sk<<<(M_ * C_ / 4) / 256, 256>>>(part, b_proj, out, M_ * C_, C_, 8);
}